// round 8
// baseline (speedup 1.0000x reference)
#include <cuda_runtime.h>

// ---------------------------------------------------------------------------
// MultiAttnMatch: QKV projections + masked cross-attention, all fp32.
// B=16, L1=L2=1024, DIN=1024, H=16, DK=DV=64
//
// Stage 1: proj_kernel (SGEMM 128x128x16) computes
//   Q = (x @ Wq + bq) * (1/sqrt(DK))   stored d-major  [B,H,DK,L1]
//   K = (y @ Wk + bk)                  stored d-major  [B,H,DK,L2]
//   V = (y @ Wv + bv)                  stored natural  [B,H,L2,DV]
// Stage 2: attn_kernel (flash-style, fp32) computes softmax(QK^T + mask) V
//   directly into d_out laid out [B, L1, H*DV].
//
// y_mask is read as int32 (JAX bool serialized as int32; True => masked).
// ---------------------------------------------------------------------------

#define B_    16
#define L_    1024
#define DIN_  1024
#define H_    16
#define DK_   64
#define NPROJ 1024   // H*DK

// Scratch (no allocations allowed -> device globals). 64 MB each.
__device__ float g_Q[B_ * H_ * DK_ * L_];   // [b][h][d][l]
__device__ float g_K[B_ * H_ * DK_ * L_];   // [b][h][d][l]
__device__ float g_V[B_ * H_ * L_ * DK_];   // [b][h][l][d]

// ---------------------------------------------------------------------------
// Projection GEMM: C[16384,1024] = A[16384,1024] @ W[1024,1024] (+bias)*scale
// which: 0 -> g_Q (transposed epilogue), 1 -> g_K (transposed), 2 -> g_V (natural)
// ---------------------------------------------------------------------------
__global__ void __launch_bounds__(256) proj_kernel(
    const float* __restrict__ A, const float* __restrict__ W,
    const float* __restrict__ bias, int which, float scale)
{
    __shared__ float As[16][128];   // As[k][m] (transposed on store)
    __shared__ float Bs[16][132];   // Bs[k][n] (padded row)

    float* out = (which == 0) ? g_Q : (which == 1) ? g_K : g_V;

    const int t  = threadIdx.x;
    const int tx = t & 15;          // 16 col-groups of 8
    const int ty = t >> 4;          // 16 row-groups of 8
    const int bm = blockIdx.y;      // 0..127
    const int bn = blockIdx.x;      // 0..7

    const float* Ab = A + (size_t)bm * 128 * DIN_;
    const float* Wb = W + bn * 128;

    float acc[8][8];
    #pragma unroll
    for (int i = 0; i < 8; i++)
        #pragma unroll
        for (int j = 0; j < 8; j++) acc[i][j] = 0.f;

    for (int kt = 0; kt < DIN_; kt += 16) {
        // Load A tile (128 x 16), transpose into As[k][m]
        #pragma unroll
        for (int i = 0; i < 2; i++) {
            int s  = t + i * 256;           // 0..511
            int r  = s >> 2;                // row 0..127
            int kq = s & 3;                 // float4 index along k
            float4 v = *(const float4*)(Ab + (size_t)r * DIN_ + kt + kq * 4);
            As[kq * 4 + 0][r] = v.x;
            As[kq * 4 + 1][r] = v.y;
            As[kq * 4 + 2][r] = v.z;
            As[kq * 4 + 3][r] = v.w;
        }
        // Load W tile (16 x 128) natural
        #pragma unroll
        for (int i = 0; i < 2; i++) {
            int s  = t + i * 256;
            int kr = s >> 5;                // 0..15
            int nq = s & 31;                // float4 col
            *(float4*)&Bs[kr][nq * 4] =
                *(const float4*)(Wb + (size_t)(kt + kr) * NPROJ + nq * 4);
        }
        __syncthreads();

        #pragma unroll
        for (int kk = 0; kk < 16; kk++) {
            float a[8], b[8];
            *(float4*)(a)     = *(const float4*)&As[kk][ty * 8];
            *(float4*)(a + 4) = *(const float4*)&As[kk][ty * 8 + 4];
            *(float4*)(b)     = *(const float4*)&Bs[kk][tx * 8];
            *(float4*)(b + 4) = *(const float4*)&Bs[kk][tx * 8 + 4];
            #pragma unroll
            for (int i = 0; i < 8; i++)
                #pragma unroll
                for (int j = 0; j < 8; j++)
                    acc[i][j] += a[i] * b[j];
        }
        __syncthreads();
    }

    const int gm0 = bm * 128 + ty * 8;   // global row (b*L + l)
    const int gn0 = bn * 128 + tx * 8;   // global col (h*DK + d)
    const int bI  = gm0 >> 10;           // batch (constant across the 8 rows)
    const int l0  = gm0 & 1023;

    if (which <= 1) {
        // d-major: out[((b*H + h)*DK + d)*L + l], vectorize over l (rows)
        #pragma unroll
        for (int j = 0; j < 8; j++) {
            int n = gn0 + j;
            int h = n >> 6, d = n & 63;
            float bb = bias[n];
            float* o = out + (((size_t)(bI * H_ + h) * DK_ + d) * L_ + l0);
            float4 v0, v1;
            v0.x = (acc[0][j] + bb) * scale; v0.y = (acc[1][j] + bb) * scale;
            v0.z = (acc[2][j] + bb) * scale; v0.w = (acc[3][j] + bb) * scale;
            v1.x = (acc[4][j] + bb) * scale; v1.y = (acc[5][j] + bb) * scale;
            v1.z = (acc[6][j] + bb) * scale; v1.w = (acc[7][j] + bb) * scale;
            *(float4*)(o)     = v0;
            *(float4*)(o + 4) = v1;
        }
    } else {
        // natural: out[((b*H + h)*L + l)*DK + d], vectorize over d (cols)
        int h = gn0 >> 6, d0 = gn0 & 63;
        float bb[8];
        #pragma unroll
        for (int j = 0; j < 8; j++) bb[j] = bias[gn0 + j];
        #pragma unroll
        for (int i = 0; i < 8; i++) {
            float* o = out + (((size_t)(bI * H_ + h) * L_ + (l0 + i)) * DK_ + d0);
            float4 v0, v1;
            v0.x = acc[i][0] + bb[0]; v0.y = acc[i][1] + bb[1];
            v0.z = acc[i][2] + bb[2]; v0.w = acc[i][3] + bb[3];
            v1.x = acc[i][4] + bb[4]; v1.y = acc[i][5] + bb[5];
            v1.z = acc[i][6] + bb[6]; v1.w = acc[i][7] + bb[7];
            *(float4*)(o)     = v0;
            *(float4*)(o + 4) = v1;
        }
    }
}

// ---------------------------------------------------------------------------
// Flash attention, fp32. Grid (L1/128, H, B), 128 threads.
// Per CTA: 128 queries; loop over 16 key-blocks of 64.
// Thread (tx in [0,8), ty in [0,16)): 8x8 tile of S and of O.
// ---------------------------------------------------------------------------
#define ATTN_SMEM_FLOATS (64 * 128 + 64 * 68 + 64 * 68 + 128 * 65 + 64)
#define ATTN_SMEM_BYTES  (ATTN_SMEM_FLOATS * 4)

__global__ void __launch_bounds__(128) attn_kernel(
    const int* __restrict__ mask, float* __restrict__ out)
{
    extern __shared__ float sm[];
    float* Qt  = sm;                         // [64][128]  Qt[d][q]
    float* Kt  = Qt + 64 * 128;              // [64][68]   Kt[d][key]
    float* Vs  = Kt + 64 * 68;               // [64][68]   Vs[key][vc]
    float* Pn  = Vs + 64 * 68;               // [128][65]  Pn[q][key]
    float* pen = Pn + 128 * 65;              // [64]

    const int t  = threadIdx.x;
    const int tx = t & 7;
    const int ty = t >> 3;
    const int qt = blockIdx.x, h = blockIdx.y, b = blockIdx.z;

    const float* Qg = g_Q + (size_t)(b * H_ + h) * DK_ * L_;   // [d][l]
    const float* Kg = g_K + (size_t)(b * H_ + h) * DK_ * L_;   // [d][l]
    const float* Vg = g_V + (size_t)(b * H_ + h) * L_ * DK_;   // [l][d]
    const int* mb = mask + b * L_;

    // Load Q tile (persistent): Qt[d][q] = Qg[d][qt*128 + q]
    #pragma unroll
    for (int i = 0; i < 16; i++) {
        int s = t + i * 128;
        int d = s >> 5, qq = s & 31;
        *(float4*)&Qt[d * 128 + qq * 4] =
            *(const float4*)(Qg + (size_t)d * L_ + qt * 128 + qq * 4);
    }

    float O[8][8];
    float m[8], l[8];
    #pragma unroll
    for (int i = 0; i < 8; i++) {
        m[i] = -1e30f; l[i] = 0.f;
        #pragma unroll
        for (int j = 0; j < 8; j++) O[i][j] = 0.f;
    }

    // lane stagger for conflict-free P store
    const int lane_f = ((ty & 3) << 1) | (tx >> 2);

    for (int j0 = 0; j0 < L_; j0 += 64) {
        __syncthreads();   // previous iteration's smem reads complete

        // Load K tile d-major: Kt[d][key]
        #pragma unroll
        for (int i = 0; i < 8; i++) {
            int s = t + i * 128;
            int d = s >> 4, kq = s & 15;
            *(float4*)&Kt[d * 68 + kq * 4] =
                *(const float4*)(Kg + (size_t)d * L_ + j0 + kq * 4);
        }
        // Load V tile natural: Vs[key][vc]
        #pragma unroll
        for (int i = 0; i < 8; i++) {
            int s = t + i * 128;
            int key = s >> 4, vq = s & 15;
            *(float4*)&Vs[key * 68 + vq * 4] =
                *(const float4*)(Vg + (size_t)(j0 + key) * DK_ + vq * 4);
        }
        if (t < 64) pen[t] = (mb[j0 + t] != 0) ? -1e30f : 0.f;
        __syncthreads();

        // ---- gemm1: S = Q(scaled) @ K^T ----
        float S[8][8];
        #pragma unroll
        for (int i = 0; i < 8; i++)
            #pragma unroll
            for (int j = 0; j < 8; j++) S[i][j] = 0.f;

        #pragma unroll 16
        for (int kk = 0; kk < 64; kk++) {
            float a[8], k[8];
            *(float4*)(a)     = *(const float4*)&Qt[kk * 128 + ty * 8];
            *(float4*)(a + 4) = *(const float4*)&Qt[kk * 128 + ty * 8 + 4];
            *(float4*)(k)     = *(const float4*)&Kt[kk * 68 + tx * 8];
            *(float4*)(k + 4) = *(const float4*)&Kt[kk * 68 + tx * 8 + 4];
            #pragma unroll
            for (int i = 0; i < 8; i++)
                #pragma unroll
                for (int j = 0; j < 8; j++)
                    S[i][j] += a[i] * k[j];
        }

        // mask penalty
        float pf[8];
        #pragma unroll
        for (int j = 0; j < 8; j++) pf[j] = pen[tx * 8 + j];
        #pragma unroll
        for (int i = 0; i < 8; i++)
            #pragma unroll
            for (int j = 0; j < 8; j++) S[i][j] += pf[j];

        // ---- online softmax update (row reduce across 8-lane tx group) ----
        #pragma unroll
        for (int i = 0; i < 8; i++) {
            float rm = S[i][0];
            #pragma unroll
            for (int j = 1; j < 8; j++) rm = fmaxf(rm, S[i][j]);
            rm = fmaxf(rm, __shfl_xor_sync(0xffffffffu, rm, 1));
            rm = fmaxf(rm, __shfl_xor_sync(0xffffffffu, rm, 2));
            rm = fmaxf(rm, __shfl_xor_sync(0xffffffffu, rm, 4));
            float mnew = fmaxf(m[i], rm);
            float corr = __expf(m[i] - mnew);
            m[i] = mnew;
            float rs = 0.f;
            #pragma unroll
            for (int j = 0; j < 8; j++) {
                float p = __expf(S[i][j] - mnew);
                S[i][j] = p;
                rs += p;
            }
            rs += __shfl_xor_sync(0xffffffffu, rs, 1);
            rs += __shfl_xor_sync(0xffffffffu, rs, 2);
            rs += __shfl_xor_sync(0xffffffffu, rs, 4);
            l[i] = l[i] * corr + rs;
            #pragma unroll
            for (int v = 0; v < 8; v++) O[i][v] *= corr;
        }

        // ---- store P to smem (lane-staggered, conflict-free) ----
        #pragma unroll
        for (int i2 = 0; i2 < 8; i2++) {
            int ii = (i2 + lane_f) & 7;
            #pragma unroll
            for (int j = 0; j < 8; j++)
                Pn[(ty * 8 + ii) * 65 + tx * 8 + j] = S[ii][j];
        }
        __syncthreads();

        // ---- gemm2: O += P @ V ----
        #pragma unroll 8
        for (int j = 0; j < 64; j++) {
            float pr[8], vf[8];
            #pragma unroll
            for (int i = 0; i < 8; i++) pr[i] = Pn[(ty * 8 + i) * 65 + j];
            *(float4*)(vf)     = *(const float4*)&Vs[j * 68 + tx * 8];
            *(float4*)(vf + 4) = *(const float4*)&Vs[j * 68 + tx * 8 + 4];
            #pragma unroll
            for (int i = 0; i < 8; i++)
                #pragma unroll
                for (int v = 0; v < 8; v++)
                    O[i][v] += pr[i] * vf[v];
        }
    }

    // ---- epilogue: normalize, write out[b, q, h*64 + vc] ----
    #pragma unroll
    for (int i = 0; i < 8; i++) {
        float inv = 1.f / l[i];
        int q = qt * 128 + ty * 8 + i;
        float* o = out + ((size_t)(b * L_ + q) * NPROJ) + h * 64 + tx * 8;
        float4 v0, v1;
        v0.x = O[i][0] * inv; v0.y = O[i][1] * inv;
        v0.z = O[i][2] * inv; v0.w = O[i][3] * inv;
        v1.x = O[i][4] * inv; v1.y = O[i][5] * inv;
        v1.z = O[i][6] * inv; v1.w = O[i][7] * inv;
        *(float4*)(o)     = v0;
        *(float4*)(o + 4) = v1;
    }
}

// ---------------------------------------------------------------------------
extern "C" void kernel_launch(void* const* d_in, const int* in_sizes, int n_in,
                              void* d_out, int out_size)
{
    const float* x     = (const float*)d_in[0];
    const float* y     = (const float*)d_in[1];
    const int*   ymask = (const int*)d_in[2];     // bool serialized as int32
    const float* Wq    = (const float*)d_in[3];
    const float* bq    = (const float*)d_in[4];
    const float* Wk    = (const float*)d_in[5];
    const float* bk    = (const float*)d_in[6];
    const float* Wv    = (const float*)d_in[7];
    const float* bv    = (const float*)d_in[8];
    float*       out   = (float*)d_out;

    cudaFuncSetAttribute(attn_kernel,
                         cudaFuncAttributeMaxDynamicSharedMemorySize,
                         ATTN_SMEM_BYTES);

    dim3 pgrid(8, 128);   // (N/128, M/128)
    proj_kernel<<<pgrid, 256>>>(x, Wq, bq, 0, 0.125f);  // Q, scaled 1/sqrt(64)
    proj_kernel<<<pgrid, 256>>>(y, Wk, bk, 1, 1.0f);    // K
    proj_kernel<<<pgrid, 256>>>(y, Wv, bv, 2, 1.0f);    // V

    attn_kernel<<<dim3(L_ / 128, H_, B_), 128, ATTN_SMEM_BYTES>>>(ymask, out);
}

// round 9
// speedup vs baseline: 1.7139x; 1.7139x over previous
#include <cuda_runtime.h>

// ---------------------------------------------------------------------------
// MultiAttnMatch: QKV projections + masked cross-attention, fp32 with
// Blackwell packed f32x2 FMA (fma.rn.f32x2) + mask compaction.
// B=16, L1=L2=1024, DIN=1024, H=16, DK=DV=64
//
//   compact_mask: per-batch list of unmasked key positions (g_idx, g_cnt)
//   proj_kernel : Q full (scaled, d-major), K/V gathered over unmasked rows
//                 (K d-major [b][h][d][r], V natural [b][h][r][d], r = compact idx)
//   attn_kernel : flash softmax over compacted keys only
// ---------------------------------------------------------------------------

#define B_    16
#define L_    1024
#define DIN_  1024
#define H_    16
#define DK_   64
#define NPROJ 1024   // H*DK

__device__ float g_Q[B_ * H_ * DK_ * L_];   // [b][h][d][l]
__device__ float g_K[B_ * H_ * DK_ * L_];   // [b][h][d][r]  (r = compacted)
__device__ float g_V[B_ * H_ * L_ * DK_];   // [b][h][r][d]
__device__ int   g_idx[B_ * L_];
__device__ int   g_cnt[B_];

// ---- packed fp32x2 helpers -------------------------------------------------
__device__ __forceinline__ unsigned long long dup2(float x) {
    unsigned long long d;
    asm("mov.b64 %0, {%1, %1};" : "=l"(d) : "f"(x));
    return d;
}
__device__ __forceinline__ unsigned long long pack2(float lo, float hi) {
    unsigned long long d;
    asm("mov.b64 %0, {%1, %2};" : "=l"(d) : "f"(lo), "f"(hi));
    return d;
}
__device__ __forceinline__ void fma2(unsigned long long& d,
                                     unsigned long long a, unsigned long long b) {
    asm("fma.rn.f32x2 %0, %1, %2, %0;" : "+l"(d) : "l"(a), "l"(b));
}
__device__ __forceinline__ void mul2(unsigned long long& d, unsigned long long a) {
    asm("mul.rn.f32x2 %0, %0, %1;" : "+l"(d) : "l"(a));
}
__device__ __forceinline__ void unpack2(unsigned long long v, float& lo, float& hi) {
    asm("mov.b64 {%0, %1}, %2;" : "=f"(lo), "=f"(hi) : "l"(v));
}

// ---------------------------------------------------------------------------
// Ballot compaction of unmasked positions, ascending order. 1 warp per batch.
// ---------------------------------------------------------------------------
__global__ void compact_mask(const int* __restrict__ mask)
{
    int b = blockIdx.x, lane = threadIdx.x;
    const int* mb = mask + b * L_;
    int base = 0;
    for (int c = 0; c < L_; c += 32) {
        int keep = (mb[c + lane] == 0);
        unsigned bal = __ballot_sync(0xffffffffu, keep);
        int pos = base + __popc(bal & ((1u << lane) - 1u));
        if (keep) g_idx[b * L_ + pos] = c + lane;
        base += __popc(bal);
    }
    if (lane == 0) g_cnt[b] = base;
}

// ---------------------------------------------------------------------------
// Projection GEMM 128x128x16, packed f32x2 inner product.
// gather=0: rows = natural l (Q). gather=1: rows = g_idx[b][r] (K/V), tiles
// entirely past g_cnt[b] exit early.
// ---------------------------------------------------------------------------
__global__ void __launch_bounds__(256) proj_kernel(
    const float* __restrict__ A, const float* __restrict__ W,
    const float* __restrict__ bias, int which, float scale, int gather)
{
    __shared__ float As[16][128];   // As[k][m]
    __shared__ float Bs[16][132];   // Bs[k][n]

    float* out = (which == 0) ? g_Q : (which == 1) ? g_K : g_V;

    const int t  = threadIdx.x;
    const int tx = t & 15;
    const int ty = t >> 4;
    const int b  = blockIdx.y >> 3;
    const int r0 = (blockIdx.y & 7) * 128;
    const int bn = blockIdx.x;

    const int cnt = gather ? g_cnt[b] : L_;
    if (r0 >= cnt) return;

    const float* Wb = W + bn * 128;

    // per-thread source row pointers (2 rows per thread, fixed across k)
    const float* Arow[2];
    int rl[2], kq[2];
    #pragma unroll
    for (int i = 0; i < 2; i++) {
        int s = t + i * 256;
        rl[i] = s >> 2;
        kq[i] = s & 3;
        int r = r0 + rl[i];
        int src;
        if (gather) {
            src = g_idx[b * L_ + ((r < cnt) ? r : 0)] & (L_ - 1);
        } else {
            src = r;
        }
        Arow[i] = A + ((size_t)b * L_ + src) * DIN_ + kq[i] * 4;
    }

    unsigned long long acc2[8][4];
    #pragma unroll
    for (int i = 0; i < 8; i++)
        #pragma unroll
        for (int j = 0; j < 4; j++) acc2[i][j] = 0ull;

    for (int kt = 0; kt < DIN_; kt += 16) {
        #pragma unroll
        for (int i = 0; i < 2; i++) {
            float4 v = *(const float4*)(Arow[i] + kt);
            As[kq[i] * 4 + 0][rl[i]] = v.x;
            As[kq[i] * 4 + 1][rl[i]] = v.y;
            As[kq[i] * 4 + 2][rl[i]] = v.z;
            As[kq[i] * 4 + 3][rl[i]] = v.w;
        }
        #pragma unroll
        for (int i = 0; i < 2; i++) {
            int s  = t + i * 256;
            int kr = s >> 5, nq = s & 31;
            *(float4*)&Bs[kr][nq * 4] =
                *(const float4*)(Wb + (size_t)(kt + kr) * NPROJ + nq * 4);
        }
        __syncthreads();

        #pragma unroll
        for (int kk = 0; kk < 16; kk++) {
            float a[8], w[8];
            *(float4*)(a)     = *(const float4*)&As[kk][ty * 8];
            *(float4*)(a + 4) = *(const float4*)&As[kk][ty * 8 + 4];
            *(float4*)(w)     = *(const float4*)&Bs[kk][tx * 8];
            *(float4*)(w + 4) = *(const float4*)&Bs[kk][tx * 8 + 4];
            unsigned long long w2[4], a2[8];
            #pragma unroll
            for (int j2 = 0; j2 < 4; j2++) w2[j2] = pack2(w[2 * j2], w[2 * j2 + 1]);
            #pragma unroll
            for (int i = 0; i < 8; i++) a2[i] = dup2(a[i]);
            #pragma unroll
            for (int i = 0; i < 8; i++)
                #pragma unroll
                for (int j2 = 0; j2 < 4; j2++)
                    fma2(acc2[i][j2], a2[i], w2[j2]);
        }
        __syncthreads();
    }

    float acc[8][8];
    #pragma unroll
    for (int i = 0; i < 8; i++)
        #pragma unroll
        for (int j2 = 0; j2 < 4; j2++)
            unpack2(acc2[i][j2], acc[i][2 * j2], acc[i][2 * j2 + 1]);

    const int gn0 = bn * 128 + tx * 8;   // col (h*DK + d)
    const int l0  = r0 + ty * 8;         // row index (compacted pos for K/V)

    if (which <= 1) {
        // d-major: out[((b*H + h)*DK + d)*L + l]
        #pragma unroll
        for (int j = 0; j < 8; j++) {
            int n = gn0 + j;
            int h = n >> 6, d = n & 63;
            float bb = bias[n];
            float* o = out + (((size_t)(b * H_ + h) * DK_ + d) * L_ + l0);
            float4 v0, v1;
            v0.x = (acc[0][j] + bb) * scale; v0.y = (acc[1][j] + bb) * scale;
            v0.z = (acc[2][j] + bb) * scale; v0.w = (acc[3][j] + bb) * scale;
            v1.x = (acc[4][j] + bb) * scale; v1.y = (acc[5][j] + bb) * scale;
            v1.z = (acc[6][j] + bb) * scale; v1.w = (acc[7][j] + bb) * scale;
            *(float4*)(o)     = v0;
            *(float4*)(o + 4) = v1;
        }
    } else {
        // natural: out[((b*H + h)*L + r)*DK + d]
        int h = gn0 >> 6, d0 = gn0 & 63;
        float bb[8];
        #pragma unroll
        for (int j = 0; j < 8; j++) bb[j] = bias[gn0 + j];
        #pragma unroll
        for (int i = 0; i < 8; i++) {
            float* o = out + (((size_t)(b * H_ + h) * L_ + (l0 + i)) * DK_ + d0);
            float4 v0, v1;
            v0.x = acc[i][0] + bb[0]; v0.y = acc[i][1] + bb[1];
            v0.z = acc[i][2] + bb[2]; v0.w = acc[i][3] + bb[3];
            v1.x = acc[i][4] + bb[4]; v1.y = acc[i][5] + bb[5];
            v1.z = acc[i][6] + bb[6]; v1.w = acc[i][7] + bb[7];
            *(float4*)(o)     = v0;
            *(float4*)(o + 4) = v1;
        }
    }
}

// ---------------------------------------------------------------------------
// Flash attention over compacted keys. Grid (L1/128, H, B), 128 threads.
// Packed f32x2 in both gemms.
// ---------------------------------------------------------------------------
#define ATTN_SMEM_FLOATS (64 * 128 + 64 * 68 + 64 * 68 + 128 * 65)
#define ATTN_SMEM_BYTES  (ATTN_SMEM_FLOATS * 4)

__global__ void __launch_bounds__(128) attn_kernel(float* __restrict__ out)
{
    extern __shared__ float sm[];
    float* Qt = sm;                 // [64][128]  Qt[d][q]
    float* Kt = Qt + 64 * 128;      // [64][68]   Kt[d][key]
    float* Vs = Kt + 64 * 68;       // [64][68]   Vs[key][vc]
    float* Pn = Vs + 64 * 68;       // [128][65]  Pn[q][key]

    const int t  = threadIdx.x;
    const int tx = t & 7;
    const int ty = t >> 3;
    const int qt = blockIdx.x, h = blockIdx.y, b = blockIdx.z;

    const float* Qg = g_Q + (size_t)(b * H_ + h) * DK_ * L_;
    const float* Kg = g_K + (size_t)(b * H_ + h) * DK_ * L_;
    const float* Vg = g_V + (size_t)(b * H_ + h) * L_ * DK_;
    const int cnt = g_cnt[b];

    // Load Q tile (persistent)
    #pragma unroll
    for (int i = 0; i < 16; i++) {
        int s = t + i * 128;
        int d = s >> 5, qq = s & 31;
        *(float4*)&Qt[d * 128 + qq * 4] =
            *(const float4*)(Qg + (size_t)d * L_ + qt * 128 + qq * 4);
    }

    unsigned long long O2[8][4];
    float m[8], l[8];
    #pragma unroll
    for (int i = 0; i < 8; i++) {
        m[i] = -1e30f; l[i] = 0.f;
        #pragma unroll
        for (int j = 0; j < 4; j++) O2[i][j] = 0ull;
    }

    const int lane_f = ((ty & 3) << 1) | (tx >> 2);

    for (int j0 = 0; j0 < cnt; j0 += 64) {
        __syncthreads();

        #pragma unroll
        for (int i = 0; i < 8; i++) {
            int s = t + i * 128;
            int d = s >> 4, kq = s & 15;
            *(float4*)&Kt[d * 68 + kq * 4] =
                *(const float4*)(Kg + (size_t)d * L_ + j0 + kq * 4);
        }
        #pragma unroll
        for (int i = 0; i < 8; i++) {
            int s = t + i * 128;
            int key = s >> 4, vq = s & 15;
            *(float4*)&Vs[key * 68 + vq * 4] =
                *(const float4*)(Vg + (size_t)(j0 + key) * DK_ + vq * 4);
        }
        __syncthreads();

        // ---- gemm1: S = Q @ K^T (packed over key dim) ----
        unsigned long long S2[8][4];
        #pragma unroll
        for (int i = 0; i < 8; i++)
            #pragma unroll
            for (int j = 0; j < 4; j++) S2[i][j] = 0ull;

        #pragma unroll 16
        for (int kk = 0; kk < 64; kk++) {
            float a[8], k[8];
            *(float4*)(a)     = *(const float4*)&Qt[kk * 128 + ty * 8];
            *(float4*)(a + 4) = *(const float4*)&Qt[kk * 128 + ty * 8 + 4];
            *(float4*)(k)     = *(const float4*)&Kt[kk * 68 + tx * 8];
            *(float4*)(k + 4) = *(const float4*)&Kt[kk * 68 + tx * 8 + 4];
            unsigned long long k2[4], a2[8];
            #pragma unroll
            for (int j2 = 0; j2 < 4; j2++) k2[j2] = pack2(k[2 * j2], k[2 * j2 + 1]);
            #pragma unroll
            for (int i = 0; i < 8; i++) a2[i] = dup2(a[i]);
            #pragma unroll
            for (int i = 0; i < 8; i++)
                #pragma unroll
                for (int j2 = 0; j2 < 4; j2++)
                    fma2(S2[i][j2], a2[i], k2[j2]);
        }

        float S[8][8];
        #pragma unroll
        for (int i = 0; i < 8; i++)
            #pragma unroll
            for (int j2 = 0; j2 < 4; j2++)
                unpack2(S2[i][j2], S[i][2 * j2], S[i][2 * j2 + 1]);

        // tail predicate: compacted keys are all valid except padding
        float pf[8];
        #pragma unroll
        for (int j = 0; j < 8; j++)
            pf[j] = (j0 + tx * 8 + j < cnt) ? 0.f : -1e30f;
        #pragma unroll
        for (int i = 0; i < 8; i++)
            #pragma unroll
            for (int j = 0; j < 8; j++) S[i][j] += pf[j];

        // ---- online softmax ----
        #pragma unroll
        for (int i = 0; i < 8; i++) {
            float rm = S[i][0];
            #pragma unroll
            for (int j = 1; j < 8; j++) rm = fmaxf(rm, S[i][j]);
            rm = fmaxf(rm, __shfl_xor_sync(0xffffffffu, rm, 1));
            rm = fmaxf(rm, __shfl_xor_sync(0xffffffffu, rm, 2));
            rm = fmaxf(rm, __shfl_xor_sync(0xffffffffu, rm, 4));
            float mnew = fmaxf(m[i], rm);
            float corr = __expf(m[i] - mnew);
            m[i] = mnew;
            float rs = 0.f;
            #pragma unroll
            for (int j = 0; j < 8; j++) {
                float p = __expf(S[i][j] - mnew);
                S[i][j] = p;
                rs += p;
            }
            rs += __shfl_xor_sync(0xffffffffu, rs, 1);
            rs += __shfl_xor_sync(0xffffffffu, rs, 2);
            rs += __shfl_xor_sync(0xffffffffu, rs, 4);
            l[i] = l[i] * corr + rs;
            unsigned long long c2 = dup2(corr);
            #pragma unroll
            for (int v = 0; v < 4; v++) mul2(O2[i][v], c2);
        }

        // ---- store P (lane-staggered, conflict-free) ----
        #pragma unroll
        for (int i2 = 0; i2 < 8; i2++) {
            int ii = (i2 + lane_f) & 7;
            #pragma unroll
            for (int j = 0; j < 8; j++)
                Pn[(ty * 8 + ii) * 65 + tx * 8 + j] = S[ii][j];
        }
        __syncthreads();

        // ---- gemm2: O += P @ V (packed over v dim) ----
        #pragma unroll 8
        for (int j = 0; j < 64; j++) {
            float pr[8], vf[8];
            #pragma unroll
            for (int i = 0; i < 8; i++) pr[i] = Pn[(ty * 8 + i) * 65 + j];
            *(float4*)(vf)     = *(const float4*)&Vs[j * 68 + tx * 8];
            *(float4*)(vf + 4) = *(const float4*)&Vs[j * 68 + tx * 8 + 4];
            unsigned long long v2[4], p2[8];
            #pragma unroll
            for (int v = 0; v < 4; v++) v2[v] = pack2(vf[2 * v], vf[2 * v + 1]);
            #pragma unroll
            for (int i = 0; i < 8; i++) p2[i] = dup2(pr[i]);
            #pragma unroll
            for (int i = 0; i < 8; i++)
                #pragma unroll
                for (int v = 0; v < 4; v++)
                    fma2(O2[i][v], p2[i], v2[v]);
        }
    }

    // ---- epilogue ----
    #pragma unroll
    for (int i = 0; i < 8; i++) {
        float O[8];
        #pragma unroll
        for (int v = 0; v < 4; v++) unpack2(O2[i][v], O[2 * v], O[2 * v + 1]);
        float inv = 1.f / l[i];
        int q = qt * 128 + ty * 8 + i;
        float* o = out + ((size_t)(b * L_ + q) * NPROJ) + h * 64 + tx * 8;
        float4 v0, v1;
        v0.x = O[0] * inv; v0.y = O[1] * inv;
        v0.z = O[2] * inv; v0.w = O[3] * inv;
        v1.x = O[4] * inv; v1.y = O[5] * inv;
        v1.z = O[6] * inv; v1.w = O[7] * inv;
        *(float4*)(o)     = v0;
        *(float4*)(o + 4) = v1;
    }
}

// ---------------------------------------------------------------------------
extern "C" void kernel_launch(void* const* d_in, const int* in_sizes, int n_in,
                              void* d_out, int out_size)
{
    const float* x     = (const float*)d_in[0];
    const float* y     = (const float*)d_in[1];
    const int*   ymask = (const int*)d_in[2];
    const float* Wq    = (const float*)d_in[3];
    const float* bq    = (const float*)d_in[4];
    const float* Wk    = (const float*)d_in[5];
    const float* bk    = (const float*)d_in[6];
    const float* Wv    = (const float*)d_in[7];
    const float* bv    = (const float*)d_in[8];
    float*       out   = (float*)d_out;

    cudaFuncSetAttribute(attn_kernel,
                         cudaFuncAttributeMaxDynamicSharedMemorySize,
                         ATTN_SMEM_BYTES);

    compact_mask<<<B_, 32>>>(ymask);

    dim3 pgrid(8, 128);
    proj_kernel<<<pgrid, 256>>>(x, Wq, bq, 0, 0.125f, 0);  // Q full, scaled
    proj_kernel<<<pgrid, 256>>>(y, Wk, bk, 1, 1.0f, 1);    // K gathered
    proj_kernel<<<pgrid, 256>>>(y, Wv, bv, 2, 1.0f, 1);    // V gathered

    attn_kernel<<<dim3(L_ / 128, H_, B_), 128, ATTN_SMEM_BYTES>>>(out);
}

// round 11
// speedup vs baseline: 1.7493x; 1.0206x over previous
#include <cuda_runtime.h>

// ---------------------------------------------------------------------------
// MultiAttnMatch: QKV projections + masked cross-attention, fp32 with
// Blackwell packed f32x2 FMA (fma.rn.f32x2) + mask compaction.
// B=16, L1=L2=1024, DIN=1024, H=16, DK=DV=64
//
//   compact_mask: per-batch list of unmasked key positions (g_idx, g_cnt)
//   proj_kernel : Q full (scaled, d-major), K/V gathered over unmasked rows
//   attn_kernel : flash softmax over compacted keys, vectorized P exchange
// ---------------------------------------------------------------------------

#define B_    16
#define L_    1024
#define DIN_  1024
#define H_    16
#define DK_   64
#define NPROJ 1024   // H*DK

__device__ float g_Q[B_ * H_ * DK_ * L_];   // [b][h][d][l]
__device__ float g_K[B_ * H_ * DK_ * L_];   // [b][h][d][r]  (r = compacted)
__device__ float g_V[B_ * H_ * L_ * DK_];   // [b][h][r][d]
__device__ int   g_idx[B_ * L_];
__device__ int   g_cnt[B_];

// ---- packed fp32x2 helpers -------------------------------------------------
__device__ __forceinline__ unsigned long long dup2(float x) {
    unsigned long long d;
    asm("mov.b64 %0, {%1, %1};" : "=l"(d) : "f"(x));
    return d;
}
__device__ __forceinline__ unsigned long long pack2(float lo, float hi) {
    unsigned long long d;
    asm("mov.b64 %0, {%1, %2};" : "=l"(d) : "f"(lo), "f"(hi));
    return d;
}
__device__ __forceinline__ void fma2(unsigned long long& d,
                                     unsigned long long a, unsigned long long b) {
    asm("fma.rn.f32x2 %0, %1, %2, %0;" : "+l"(d) : "l"(a), "l"(b));
}
__device__ __forceinline__ void mul2(unsigned long long& d, unsigned long long a) {
    asm("mul.rn.f32x2 %0, %0, %1;" : "+l"(d) : "l"(a));
}
__device__ __forceinline__ void unpack2(unsigned long long v, float& lo, float& hi) {
    asm("mov.b64 {%0, %1}, %2;" : "=f"(lo), "=f"(hi) : "l"(v));
}

// ---------------------------------------------------------------------------
// Ballot compaction of unmasked positions, ascending order. 1 warp per batch.
// ---------------------------------------------------------------------------
__global__ void compact_mask(const int* __restrict__ mask)
{
    int b = blockIdx.x, lane = threadIdx.x;
    const int* mb = mask + b * L_;
    int base = 0;
    for (int c = 0; c < L_; c += 32) {
        int keep = (mb[c + lane] == 0);
        unsigned bal = __ballot_sync(0xffffffffu, keep);
        int pos = base + __popc(bal & ((1u << lane) - 1u));
        if (keep) g_idx[b * L_ + pos] = c + lane;
        base += __popc(bal);
    }
    if (lane == 0) g_cnt[b] = base;
}

// ---------------------------------------------------------------------------
// Projection GEMM 128x128x16, packed f32x2 inner product.
// gather=0: rows = natural l (Q). gather=1: rows = g_idx[b][r] (K/V).
// ---------------------------------------------------------------------------
__global__ void __launch_bounds__(256) proj_kernel(
    const float* __restrict__ A, const float* __restrict__ W,
    const float* __restrict__ bias, int which, float scale, int gather)
{
    __shared__ float As[16][128];   // As[k][m]
    __shared__ float Bs[16][132];   // Bs[k][n]

    float* out = (which == 0) ? g_Q : (which == 1) ? g_K : g_V;

    const int t  = threadIdx.x;
    const int tx = t & 15;
    const int ty = t >> 4;
    const int b  = blockIdx.y >> 3;
    const int r0 = (blockIdx.y & 7) * 128;
    const int bn = blockIdx.x;

    const int cnt = gather ? g_cnt[b] : L_;
    if (r0 >= cnt) return;

    const float* Wb = W + bn * 128;

    const float* Arow[2];
    int rl[2], kq[2];
    #pragma unroll
    for (int i = 0; i < 2; i++) {
        int s = t + i * 256;
        rl[i] = s >> 2;
        kq[i] = s & 3;
        int r = r0 + rl[i];
        int src;
        if (gather) {
            src = g_idx[b * L_ + ((r < cnt) ? r : 0)] & (L_ - 1);
        } else {
            src = r;
        }
        Arow[i] = A + ((size_t)b * L_ + src) * DIN_ + kq[i] * 4;
    }

    unsigned long long acc2[8][4];
    #pragma unroll
    for (int i = 0; i < 8; i++)
        #pragma unroll
        for (int j = 0; j < 4; j++) acc2[i][j] = 0ull;

    for (int kt = 0; kt < DIN_; kt += 16) {
        #pragma unroll
        for (int i = 0; i < 2; i++) {
            float4 v = *(const float4*)(Arow[i] + kt);
            As[kq[i] * 4 + 0][rl[i]] = v.x;
            As[kq[i] * 4 + 1][rl[i]] = v.y;
            As[kq[i] * 4 + 2][rl[i]] = v.z;
            As[kq[i] * 4 + 3][rl[i]] = v.w;
        }
        #pragma unroll
        for (int i = 0; i < 2; i++) {
            int s  = t + i * 256;
            int kr = s >> 5, nq = s & 31;
            *(float4*)&Bs[kr][nq * 4] =
                *(const float4*)(Wb + (size_t)(kt + kr) * NPROJ + nq * 4);
        }
        __syncthreads();

        #pragma unroll
        for (int kk = 0; kk < 16; kk++) {
            float a[8], w[8];
            *(float4*)(a)     = *(const float4*)&As[kk][ty * 8];
            *(float4*)(a + 4) = *(const float4*)&As[kk][ty * 8 + 4];
            *(float4*)(w)     = *(const float4*)&Bs[kk][tx * 8];
            *(float4*)(w + 4) = *(const float4*)&Bs[kk][tx * 8 + 4];
            unsigned long long w2[4], a2[8];
            #pragma unroll
            for (int j2 = 0; j2 < 4; j2++) w2[j2] = pack2(w[2 * j2], w[2 * j2 + 1]);
            #pragma unroll
            for (int i = 0; i < 8; i++) a2[i] = dup2(a[i]);
            #pragma unroll
            for (int i = 0; i < 8; i++)
                #pragma unroll
                for (int j2 = 0; j2 < 4; j2++)
                    fma2(acc2[i][j2], a2[i], w2[j2]);
        }
        __syncthreads();
    }

    float acc[8][8];
    #pragma unroll
    for (int i = 0; i < 8; i++)
        #pragma unroll
        for (int j2 = 0; j2 < 4; j2++)
            unpack2(acc2[i][j2], acc[i][2 * j2], acc[i][2 * j2 + 1]);

    const int gn0 = bn * 128 + tx * 8;   // col (h*DK + d)
    const int l0  = r0 + ty * 8;         // row index (compacted pos for K/V)

    if (which <= 1) {
        // d-major: out[((b*H + h)*DK + d)*L + l]
        #pragma unroll
        for (int j = 0; j < 8; j++) {
            int n = gn0 + j;
            int h = n >> 6, d = n & 63;
            float bb = bias[n];
            float* o = out + (((size_t)(b * H_ + h) * DK_ + d) * L_ + l0);
            float4 v0, v1;
            v0.x = (acc[0][j] + bb) * scale; v0.y = (acc[1][j] + bb) * scale;
            v0.z = (acc[2][j] + bb) * scale; v0.w = (acc[3][j] + bb) * scale;
            v1.x = (acc[4][j] + bb) * scale; v1.y = (acc[5][j] + bb) * scale;
            v1.z = (acc[6][j] + bb) * scale; v1.w = (acc[7][j] + bb) * scale;
            *(float4*)(o)     = v0;
            *(float4*)(o + 4) = v1;
        }
    } else {
        // natural: out[((b*H + h)*L + r)*DK + d]
        int h = gn0 >> 6, d0 = gn0 & 63;
        float bb[8];
        #pragma unroll
        for (int j = 0; j < 8; j++) bb[j] = bias[gn0 + j];
        #pragma unroll
        for (int i = 0; i < 8; i++) {
            float* o = out + (((size_t)(b * H_ + h) * L_ + (l0 + i)) * DK_ + d0);
            float4 v0, v1;
            v0.x = acc[i][0] + bb[0]; v0.y = acc[i][1] + bb[1];
            v0.z = acc[i][2] + bb[2]; v0.w = acc[i][3] + bb[3];
            v1.x = acc[i][4] + bb[4]; v1.y = acc[i][5] + bb[5];
            v1.z = acc[i][6] + bb[6]; v1.w = acc[i][7] + bb[7];
            *(float4*)(o)     = v0;
            *(float4*)(o + 4) = v1;
        }
    }
}

// ---------------------------------------------------------------------------
// Flash attention over compacted keys. Grid (L1/128, H, B), 128 threads.
// Packed f32x2 in both gemms; vectorized P exchange (pitch 68).
// ---------------------------------------------------------------------------
#define ATTN_SMEM_FLOATS (64 * 128 + 64 * 68 + 64 * 68 + 128 * 68)
#define ATTN_SMEM_BYTES  (ATTN_SMEM_FLOATS * 4)

__global__ void __launch_bounds__(128) attn_kernel(float* __restrict__ out)
{
    extern __shared__ float sm[];
    float* Qt = sm;                 // [64][128]  Qt[d][q]
    float* Kt = Qt + 64 * 128;      // [64][68]   Kt[d][key]
    float* Vs = Kt + 64 * 68;       // [64][68]   Vs[key][vc]
    float* Pn = Vs + 64 * 68;       // [128][68]  Pn[q][key] (16B-aligned rows)

    const int t  = threadIdx.x;
    const int tx = t & 7;
    const int ty = t >> 3;
    const int qt = blockIdx.x, h = blockIdx.y, b = blockIdx.z;

    const float* Qg = g_Q + (size_t)(b * H_ + h) * DK_ * L_;
    const float* Kg = g_K + (size_t)(b * H_ + h) * DK_ * L_;
    const float* Vg = g_V + (size_t)(b * H_ + h) * L_ * DK_;
    const int cnt = g_cnt[b];

    // Load Q tile (persistent)
    #pragma unroll
    for (int i = 0; i < 16; i++) {
        int s = t + i * 128;
        int d = s >> 5, qq = s & 31;
        *(float4*)&Qt[d * 128 + qq * 4] =
            *(const float4*)(Qg + (size_t)d * L_ + qt * 128 + qq * 4);
    }

    unsigned long long O2[8][4];
    float m[8], l[8];
    #pragma unroll
    for (int i = 0; i < 8; i++) {
        m[i] = -1e30f; l[i] = 0.f;
        #pragma unroll
        for (int j = 0; j < 4; j++) O2[i][j] = 0ull;
    }

    for (int j0 = 0; j0 < cnt; j0 += 64) {
        __syncthreads();

        #pragma unroll
        for (int i = 0; i < 8; i++) {
            int s = t + i * 128;
            int d = s >> 4, kq = s & 15;
            *(float4*)&Kt[d * 68 + kq * 4] =
                *(const float4*)(Kg + (size_t)d * L_ + j0 + kq * 4);
        }
        #pragma unroll
        for (int i = 0; i < 8; i++) {
            int s = t + i * 128;
            int key = s >> 4, vq = s & 15;
            *(float4*)&Vs[key * 68 + vq * 4] =
                *(const float4*)(Vg + (size_t)(j0 + key) * DK_ + vq * 4);
        }
        __syncthreads();

        // ---- gemm1: S = Q @ K^T (packed over key dim) ----
        unsigned long long S2[8][4];
        #pragma unroll
        for (int i = 0; i < 8; i++)
            #pragma unroll
            for (int j = 0; j < 4; j++) S2[i][j] = 0ull;

        #pragma unroll 16
        for (int kk = 0; kk < 64; kk++) {
            float a[8], k[8];
            *(float4*)(a)     = *(const float4*)&Qt[kk * 128 + ty * 8];
            *(float4*)(a + 4) = *(const float4*)&Qt[kk * 128 + ty * 8 + 4];
            *(float4*)(k)     = *(const float4*)&Kt[kk * 68 + tx * 8];
            *(float4*)(k + 4) = *(const float4*)&Kt[kk * 68 + tx * 8 + 4];
            unsigned long long k2[4], a2[8];
            #pragma unroll
            for (int j2 = 0; j2 < 4; j2++) k2[j2] = pack2(k[2 * j2], k[2 * j2 + 1]);
            #pragma unroll
            for (int i = 0; i < 8; i++) a2[i] = dup2(a[i]);
            #pragma unroll
            for (int i = 0; i < 8; i++)
                #pragma unroll
                for (int j2 = 0; j2 < 4; j2++)
                    fma2(S2[i][j2], a2[i], k2[j2]);
        }

        float S[8][8];
        #pragma unroll
        for (int i = 0; i < 8; i++)
            #pragma unroll
            for (int j2 = 0; j2 < 4; j2++)
                unpack2(S2[i][j2], S[i][2 * j2], S[i][2 * j2 + 1]);

        // tail predicate: compacted keys all valid except padding
        float pf[8];
        #pragma unroll
        for (int j = 0; j < 8; j++)
            pf[j] = (j0 + tx * 8 + j < cnt) ? 0.f : -1e30f;
        #pragma unroll
        for (int i = 0; i < 8; i++)
            #pragma unroll
            for (int j = 0; j < 8; j++) S[i][j] += pf[j];

        // ---- online softmax ----
        #pragma unroll
        for (int i = 0; i < 8; i++) {
            float rm = S[i][0];
            #pragma unroll
            for (int j = 1; j < 8; j++) rm = fmaxf(rm, S[i][j]);
            rm = fmaxf(rm, __shfl_xor_sync(0xffffffffu, rm, 1));
            rm = fmaxf(rm, __shfl_xor_sync(0xffffffffu, rm, 2));
            rm = fmaxf(rm, __shfl_xor_sync(0xffffffffu, rm, 4));
            float mnew = fmaxf(m[i], rm);
            float corr = __expf(m[i] - mnew);
            m[i] = mnew;
            float rs = 0.f;
            #pragma unroll
            for (int j = 0; j < 8; j++) {
                float p = __expf(S[i][j] - mnew);
                S[i][j] = p;
                rs += p;
            }
            rs += __shfl_xor_sync(0xffffffffu, rs, 1);
            rs += __shfl_xor_sync(0xffffffffu, rs, 2);
            rs += __shfl_xor_sync(0xffffffffu, rs, 4);
            l[i] = l[i] * corr + rs;
            unsigned long long c2 = dup2(corr);
            #pragma unroll
            for (int v = 0; v < 4; v++) mul2(O2[i][v], c2);
        }

        // ---- store P rows as float4 (2 STS.128 per row) ----
        #pragma unroll
        for (int i = 0; i < 8; i++) {
            float* pr = &Pn[(ty * 8 + i) * 68 + tx * 8];
            *(float4*)(pr)     = *(float4*)&S[i][0];
            *(float4*)(pr + 4) = *(float4*)&S[i][4];
        }
        __syncthreads();

        // ---- gemm2: O += P @ V, 4 keys per chunk, vector P loads ----
        #pragma unroll 4
        for (int j4 = 0; j4 < 64; j4 += 4) {
            float prr[8][4];
            #pragma unroll
            for (int i = 0; i < 8; i++)
                *(float4*)prr[i] = *(const float4*)&Pn[(ty * 8 + i) * 68 + j4];
            #pragma unroll
            for (int jj = 0; jj < 4; jj++) {
                int j = j4 + jj;
                float vf[8];
                *(float4*)(vf)     = *(const float4*)&Vs[j * 68 + tx * 8];
                *(float4*)(vf + 4) = *(const float4*)&Vs[j * 68 + tx * 8 + 4];
                unsigned long long v2[4];
                #pragma unroll
                for (int v = 0; v < 4; v++) v2[v] = pack2(vf[2 * v], vf[2 * v + 1]);
                #pragma unroll
                for (int i = 0; i < 8; i++) {
                    unsigned long long p2 = dup2(prr[i][jj]);
                    #pragma unroll
                    for (int v = 0; v < 4; v++)
                        fma2(O2[i][v], p2, v2[v]);
                }
            }
        }
    }

    // ---- epilogue ----
    #pragma unroll
    for (int i = 0; i < 8; i++) {
        float O[8];
        #pragma unroll
        for (int v = 0; v < 4; v++) unpack2(O2[i][v], O[2 * v], O[2 * v + 1]);
        float inv = 1.f / l[i];
        int q = qt * 128 + ty * 8 + i;
        float* o = out + ((size_t)(b * L_ + q) * NPROJ) + h * 64 + tx * 8;
        float4 v0, v1;
        v0.x = O[0] * inv; v0.y = O[1] * inv;
        v0.z = O[2] * inv; v0.w = O[3] * inv;
        v1.x = O[4] * inv; v1.y = O[5] * inv;
        v1.z = O[6] * inv; v1.w = O[7] * inv;
        *(float4*)(o)     = v0;
        *(float4*)(o + 4) = v1;
    }
}

// ---------------------------------------------------------------------------
extern "C" void kernel_launch(void* const* d_in, const int* in_sizes, int n_in,
                              void* d_out, int out_size)
{
    const float* x     = (const float*)d_in[0];
    const float* y     = (const float*)d_in[1];
    const int*   ymask = (const int*)d_in[2];
    const float* Wq    = (const float*)d_in[3];
    const float* bq    = (const float*)d_in[4];
    const float* Wk    = (const float*)d_in[5];
    const float* bk    = (const float*)d_in[6];
    const float* Wv    = (const float*)d_in[7];
    const float* bv    = (const float*)d_in[8];
    float*       out   = (float*)d_out;

    cudaFuncSetAttribute(attn_kernel,
                         cudaFuncAttributeMaxDynamicSharedMemorySize,
                         ATTN_SMEM_BYTES);

    compact_mask<<<B_, 32>>>(ymask);

    dim3 pgrid(8, 128);
    proj_kernel<<<pgrid, 256>>>(x, Wq, bq, 0, 0.125f, 0);  // Q full, scaled
    proj_kernel<<<pgrid, 256>>>(y, Wk, bk, 1, 1.0f, 1);    // K gathered
    proj_kernel<<<pgrid, 256>>>(y, Wv, bv, 2, 1.0f, 1);    // V gathered

    attn_kernel<<<dim3(L_ / 128, H_, B_), 128, ATTN_SMEM_BYTES>>>(out);
}